// round 11
// baseline (speedup 1.0000x reference)
#include <cuda_runtime.h>
#include <cuda_bf16.h>
#include <cstdint>

#define N_NODES 50000
#define N_EDGES 800000
#define HDIM    256
#define N_LAYERS 3
#define NWEIGHTS 11
#define MT 3125                 // 16-row tiles in M (50000/16 exactly)

// ---------------- scratch (no allocation allowed) ----------------
__device__ float g_xcur[N_NODES * HDIM];
__device__ uint4 g_apk[2][(size_t)MT * 16 * 2 * 32];
// packed split weights: [w][ch(8)][n8(32)][k2(2)][hi/lo][lane(32)] uint2
__device__ uint2 g_bpk[(size_t)NWEIGHTS * 8 * 32 * 2 * 2 * 32];
__device__ int   g_src [N_EDGES];
__device__ int   g_dst [N_EDGES];
__device__ float4 g_easrt[N_EDGES];      // sorted-by-dst: (a0,a1,a2, src-as-int)
__device__ int   g_cnt  [N_NODES];
__device__ int   g_start[N_NODES + 1];
__device__ int   g_fill [N_NODES];
__device__ int   g_is64;

// ---------------- helpers ----------------
__device__ __forceinline__ uint32_t smem_u32(const void* p) {
    uint32_t a;
    asm("{ .reg .u64 t; cvta.to.shared.u64 t, %1; cvt.u32.u64 %0, t; }" : "=r"(a) : "l"(p));
    return a;
}
__device__ __forceinline__ void cpa16(uint32_t dst, const void* src) {
    asm volatile("cp.async.cg.shared.global [%0], [%1], 16;" :: "r"(dst), "l"(src) : "memory");
}
__device__ __forceinline__ uint32_t pk2(float e0, float e1) {
    uint32_t r;
    asm("cvt.rn.bf16x2.f32 %0, %1, %2;" : "=r"(r) : "f"(e1), "f"(e0));
    return r;
}
__device__ __forceinline__ float lo16f(uint32_t r) { return __uint_as_float(r << 16); }
__device__ __forceinline__ float hi16f(uint32_t r) { return __uint_as_float(r & 0xFFFF0000u); }
__device__ __forceinline__ void split2(float v0, float v1, uint32_t& h, uint32_t& l) {
    h = pk2(v0, v1);
    l = pk2(v0 - lo16f(h), v1 - hi16f(h));
}
__device__ __forceinline__ void mma16(float* c, const uint4& a, uint32_t b0, uint32_t b1) {
    asm volatile("mma.sync.aligned.m16n8k16.row.col.f32.bf16.bf16.f32 "
                 "{%0,%1,%2,%3},{%4,%5,%6,%7},{%8,%9},{%0,%1,%2,%3};"
                 : "+f"(c[0]), "+f"(c[1]), "+f"(c[2]), "+f"(c[3])
                 : "r"(a.x), "r"(a.y), "r"(a.z), "r"(a.w), "r"(b0), "r"(b1));
}

// ---------------- index prep ----------------
__global__ void detect_kernel(const unsigned* __restrict__ ei) {
    if (threadIdx.x == 0 && blockIdx.x == 0) {
        int all0 = 1;
        #pragma unroll 1
        for (int i = 1; i < 128; i += 2) if (ei[i] != 0u) { all0 = 0; break; }
        g_is64 = all0;
    }
}
__global__ void convert_idx_kernel(const void* __restrict__ ei) {
    int i = blockIdx.x * blockDim.x + threadIdx.x;
    if (i >= N_EDGES) return;
    if (g_is64) {
        const long long* p = (const long long*)ei;
        g_src[i] = (int)p[i];
        g_dst[i] = (int)p[N_EDGES + i];
    } else {
        const int* p = (const int*)ei;
        g_src[i] = p[i];
        g_dst[i] = p[N_EDGES + i];
    }
}
__global__ void zero_cnt_kernel() {
    int i = blockIdx.x * blockDim.x + threadIdx.x;
    if (i < N_NODES) g_cnt[i] = 0;
}
__global__ void hist_kernel() {
    int i = blockIdx.x * blockDim.x + threadIdx.x;
    if (i < N_EDGES) atomicAdd(&g_cnt[g_dst[i]], 1);
}
#define SCAN_T 1024
#define SCAN_C 49
__global__ __launch_bounds__(SCAN_T) void scan_kernel() {
    __shared__ int ssum[SCAN_T];
    int tid = threadIdx.x;
    int base = tid * SCAN_C;
    int s = 0;
    #pragma unroll 1
    for (int j = 0; j < SCAN_C; j++) {
        int idx = base + j;
        if (idx < N_NODES) s += g_cnt[idx];
    }
    ssum[tid] = s;
    __syncthreads();
    #pragma unroll 1
    for (int off = 1; off < SCAN_T; off <<= 1) {
        int v = (tid >= off) ? ssum[tid - off] : 0;
        __syncthreads();
        ssum[tid] += v;
        __syncthreads();
    }
    int run = ssum[tid] - s;
    #pragma unroll 1
    for (int j = 0; j < SCAN_C; j++) {
        int idx = base + j;
        if (idx < N_NODES) {
            g_start[idx] = run;
            g_fill[idx]  = run;
            run += g_cnt[idx];
        }
    }
    if (tid == 0) g_start[N_NODES] = N_EDGES;
}
__global__ void scatter_kernel(const float* __restrict__ edge_attr) {
    int i = blockIdx.x * blockDim.x + threadIdx.x;
    if (i >= N_EDGES) return;
    int d = g_dst[i];
    int pos = atomicAdd(&g_fill[d], 1);
    float a0 = __ldg(&edge_attr[i * 3 + 0]);
    float a1 = __ldg(&edge_attr[i * 3 + 1]);
    float a2 = __ldg(&edge_attr[i * 3 + 2]);
    g_easrt[pos] = make_float4(a0, a1, a2, __int_as_float(g_src[i]));
}

// ---------------- copies / weight packing ----------------
__global__ void copy_kernel(const float4* __restrict__ src, float4* __restrict__ dst, int n4) {
    int i = blockIdx.x * blockDim.x + threadIdx.x;
    if (i < n4) dst[i] = src[i];
}
__global__ void prep_w(const float* __restrict__ Wm, const float* __restrict__ pW1,
                       const float* __restrict__ pW2) {
    int w = blockIdx.z, n8 = blockIdx.y, k16 = blockIdx.x;
    int lane = threadIdx.x;
    const float* src = (w < 9) ? (Wm + (size_t)w * HDIM * HDIM) : ((w == 9) ? pW1 : pW2);
    int g = lane >> 2, t = lane & 3;
    int n = n8 * 8 + g;
    int kb = k16 * 16 + t * 2;
    float v0 = src[(size_t)kb * HDIM + n],       v1 = src[(size_t)(kb + 1) * HDIM + n];
    float w0 = src[(size_t)(kb + 8) * HDIM + n], w1 = src[(size_t)(kb + 9) * HDIM + n];
    uint2 hh, ll;
    split2(v0, v1, hh.x, ll.x);
    split2(w0, w1, hh.y, ll.y);
    int ch = k16 >> 1, k2 = k16 & 1;
    size_t o = ((((size_t)w * 8 + ch) * 32 + n8) * 2 + k2) * 2 * 32 + lane;
    g_bpk[o] = hh;
    g_bpk[o + 32] = ll;
}

// ---------------- fused edge phase + bf16 split/pack ----------------
// block = one m-tile (16 nodes), 16 warps; warp-per-node register accumulation,
// SMEM staging, then in-block repack to fragment-packed hi/lo.
__global__ __launch_bounds__(512) void edge_pack(
    const float* __restrict__ x,
    const float* __restrict__ We, const float* __restrict__ be,
    uint4* __restrict__ dst)
{
    __shared__ float s[16][HDIM + 2];
    int wid = threadIdx.x >> 5, lane = threadIdx.x & 31;
    int node = blockIdx.x * 16 + wid;
    int h = lane * 8;

    float w0[8], w1[8], w2[8], bb[8];
    #pragma unroll
    for (int j = 0; j < 8; j++) {
        w0[j] = __ldg(We + h + j);
        w1[j] = __ldg(We + HDIM + h + j);
        w2[j] = __ldg(We + 2 * HDIM + h + j);
        bb[j] = __ldg(be + h + j);
    }

    float c[8];
    {
        const float4* xr = (const float4*)(x + (size_t)node * HDIM + h);
        float4 v0 = __ldg(xr), v1 = __ldg(xr + 1);
        c[0] = v0.x; c[1] = v0.y; c[2] = v0.z; c[3] = v0.w;
        c[4] = v1.x; c[5] = v1.y; c[6] = v1.z; c[7] = v1.w;
    }
    int s0 = g_start[node], s1 = g_start[node + 1];
    #pragma unroll 4
    for (int j = s0; j < s1; j++) {
        float4 ea = __ldg(&g_easrt[j]);
        int src = __float_as_int(ea.w);
        const float4* xs = (const float4*)(x + (size_t)src * HDIM + h);
        float4 v0 = __ldg(xs), v1 = __ldg(xs + 1);
        float xv[8] = {v0.x, v0.y, v0.z, v0.w, v1.x, v1.y, v1.z, v1.w};
        #pragma unroll
        for (int k = 0; k < 8; k++) {
            float e = fmaf(ea.x, w0[k], fmaf(ea.y, w1[k], fmaf(ea.z, w2[k], bb[k])));
            c[k] += fmaxf(xv[k] + e, 0.f);
        }
    }
    #pragma unroll
    for (int j = 0; j < 8; j++) s[wid][h + j] = c[j];
    __syncthreads();

    // repack: warp wid handles k16 group wid
    int g = lane >> 2, t = lane & 3;
    const float* r0 = &s[g][wid * 16 + t * 2];
    const float* r1 = &s[g + 8][wid * 16 + t * 2];
    float2 v00 = make_float2(r0[0], r0[1]), v01 = make_float2(r0[8], r0[9]);
    float2 v10 = make_float2(r1[0], r1[1]), v11 = make_float2(r1[8], r1[9]);
    uint4 hh, ll;
    split2(v00.x, v00.y, hh.x, ll.x);
    split2(v10.x, v10.y, hh.y, ll.y);
    split2(v01.x, v01.y, hh.z, ll.z);
    split2(v11.x, v11.y, hh.w, ll.w);
    size_t o = ((size_t)(blockIdx.x * 16 + wid) * 2) * 32 + lane;
    dst[o] = hh;
    dst[o + 32] = ll;
}

// ---------------- bf16-split mma GEMM (round-7 layout, 3-stage pipeline) ----------------
__global__ __launch_bounds__(256, 2) void gemm_bf(
    const uint4* __restrict__ Apk, const uint2* __restrict__ Bpk,
    const float* __restrict__ bias, float* __restrict__ Cf, uint4* __restrict__ Opk,
    const float* __restrict__ res, int mode)
{
    __shared__ uint2 sb[3][2048];           // 3 x 16KB B staging = 48KB
    const uint32_t sbase = smem_u32(sb);
    const int tid  = threadIdx.x;
    const int lane = tid & 31;
    const int warp = tid >> 5;
    const int g = lane >> 2, t = lane & 3;
    const int wm = warp & 3;
    const int wn = warp >> 2;
    const int bm = blockIdx.x * 128;
    const int bn = blockIdx.y * 128;
    const int bn8 = bn >> 3;

    float acc[2][8][4];
    #pragma unroll
    for (int i = 0; i < 2; i++)
        #pragma unroll
        for (int j = 0; j < 8; j++)
            #pragma unroll
            for (int q = 0; q < 4; q++) acc[i][j][q] = 0.f;

    const int mtA = (bm >> 4) + wm * 2;
    const bool ok0 = (mtA + 0) < MT;
    const bool ok1 = (mtA + 1) < MT;

    auto issue = [&](int ch, int buf) {
        const uint4* src = (const uint4*)(Bpk + ((size_t)ch * 32 + bn8) * 128);
        uint32_t dst = sbase + buf * 16384 + tid * 16;
        #pragma unroll
        for (int i = 0; i < 4; i++) cpa16(dst + i * 4096, src + tid + i * 256);
        asm volatile("cp.async.commit_group;" ::: "memory");
    };
    auto ldA = [&](int k16, uint4 fr[2][2]) {
        #pragma unroll
        for (int mi = 0; mi < 2; mi++) {
            bool ok = mi ? ok1 : ok0;
            size_t o = ((size_t)((mtA + mi) * 16 + k16) * 2) * 32 + lane;
            if (ok) {
                fr[mi][0] = __ldg(Apk + o);
                fr[mi][1] = __ldg(Apk + o + 32);
            } else {
                fr[mi][0] = make_uint4(0, 0, 0, 0);
                fr[mi][1] = make_uint4(0, 0, 0, 0);
            }
        }
    };

    issue(0, 0);
    issue(1, 1);
    issue(2, 2);

    uint4 af[2][2], an[2][2];
    ldA(0, af);

    #pragma unroll 1
    for (int ch = 0; ch < 8; ch++) {
        const int buf = ch % 3;
        if (ch == 7)      asm volatile("cp.async.wait_group 0;" ::: "memory");
        else if (ch == 6) asm volatile("cp.async.wait_group 1;" ::: "memory");
        else              asm volatile("cp.async.wait_group 2;" ::: "memory");
        __syncthreads();

        #pragma unroll
        for (int k2 = 0; k2 < 2; k2++) {
            const int k16 = ch * 2 + k2;
            if (k16 < 15) ldA(k16 + 1, an);
            const uint2* bs = sb[buf];
            uint2 bh[8];
            #pragma unroll
            for (int ni = 0; ni < 8; ni++)
                bh[ni] = bs[(wn * 8 + ni) * 128 + k2 * 64 + lane];
            #pragma unroll
            for (int mi = 0; mi < 2; mi++)
                #pragma unroll
                for (int ni = 0; ni < 8; ni++) {
                    mma16(acc[mi][ni], af[mi][0], bh[ni].x, bh[ni].y);
                    mma16(acc[mi][ni], af[mi][1], bh[ni].x, bh[ni].y);
                }
            uint2 bl[8];
            #pragma unroll
            for (int ni = 0; ni < 8; ni++)
                bl[ni] = bs[(wn * 8 + ni) * 128 + k2 * 64 + 32 + lane];
            #pragma unroll
            for (int mi = 0; mi < 2; mi++)
                #pragma unroll
                for (int ni = 0; ni < 8; ni++)
                    mma16(acc[mi][ni], af[mi][0], bl[ni].x, bl[ni].y);
            if (k16 < 15) {
                #pragma unroll
                for (int mi = 0; mi < 2; mi++) {
                    af[mi][0] = an[mi][0];
                    af[mi][1] = an[mi][1];
                }
            }
        }
        __syncthreads();
        if (ch + 3 < 8) issue(ch + 3, buf);
    }

    #pragma unroll
    for (int ni = 0; ni < 8; ni++) {
        int col = bn + wn * 64 + ni * 8 + t * 2;
        float2 bb = *(const float2*)(bias + col);
        #pragma unroll
        for (int mi = 0; mi < 2; mi++) {
            float* c = acc[mi][ni];
            c[0] += bb.x; c[1] += bb.y; c[2] += bb.x; c[3] += bb.y;
            if (mode >= 1) {
                c[0] = fmaxf(c[0], 0.f); c[1] = fmaxf(c[1], 0.f);
                c[2] = fmaxf(c[2], 0.f); c[3] = fmaxf(c[3], 0.f);
            }
            if (mode == 2) {
                bool ok = mi ? ok1 : ok0;
                if (ok) {
                    int row0 = bm + wm * 32 + mi * 16 + g;
                    float2 r0 = *(const float2*)(res + (size_t)row0 * HDIM + col);
                    float2 r1 = *(const float2*)(res + (size_t)(row0 + 8) * HDIM + col);
                    c[0] += r0.x; c[1] += r0.y; c[2] += r1.x; c[3] += r1.y;
                }
            }
        }
    }
    if (Cf) {
        #pragma unroll
        for (int mi = 0; mi < 2; mi++) {
            bool ok = mi ? ok1 : ok0;
            if (!ok) continue;
            int row0 = bm + wm * 32 + mi * 16 + g;
            #pragma unroll
            for (int ni = 0; ni < 8; ni++) {
                int col = bn + wn * 64 + ni * 8 + t * 2;
                float* c = acc[mi][ni];
                *(float2*)(Cf + (size_t)row0 * HDIM + col)       = make_float2(c[0], c[1]);
                *(float2*)(Cf + (size_t)(row0 + 8) * HDIM + col) = make_float2(c[2], c[3]);
            }
        }
    }
    if (Opk) {
        #pragma unroll
        for (int mi = 0; mi < 2; mi++) {
            bool ok = mi ? ok1 : ok0;
            if (!ok) continue;
            int mt = mtA + mi;
            #pragma unroll
            for (int nip = 0; nip < 4; nip++) {
                float* c0 = acc[mi][nip * 2];
                float* c1 = acc[mi][nip * 2 + 1];
                uint4 h, l;
                split2(c0[0], c0[1], h.x, l.x);
                split2(c0[2], c0[3], h.y, l.y);
                split2(c1[0], c1[1], h.z, l.z);
                split2(c1[2], c1[3], h.w, l.w);
                int k16o = (bn + wn * 64 + nip * 16) >> 4;
                size_t o = ((size_t)(mt * 16 + k16o) * 2) * 32 + lane;
                Opk[o] = h;
                Opk[o + 32] = l;
            }
        }
    }
}

// ---------------- launch ----------------
extern "C" void kernel_launch(void* const* d_in, const int* in_sizes, int n_in,
                              void* d_out, int out_size)
{
    const float* x         = (const float*)d_in[0];
    const void*  edge_idx  = d_in[1];
    const float* edge_attr = (const float*)d_in[2];
    const float* We        = (const float*)d_in[3];
    const float* be        = (const float*)d_in[4];
    const float* Wm        = (const float*)d_in[5];
    const float* bmv       = (const float*)d_in[6];
    const float* pW1       = (const float*)d_in[7];
    const float* pb1       = (const float*)d_in[8];
    const float* pW2       = (const float*)d_in[9];
    const float* pb2       = (const float*)d_in[10];
    float* out             = (float*)d_out;

    float *xcur;
    uint4 *apk;
    uint2 *bpk;
    cudaGetSymbolAddress((void**)&xcur, g_xcur);
    cudaGetSymbolAddress((void**)&apk,  g_apk);
    cudaGetSymbolAddress((void**)&bpk,  g_bpk);
    uint4* apk0 = apk;
    uint4* apk1 = apk + (size_t)MT * 16 * 2 * 32;

    const int n4 = N_NODES * HDIM / 4;
    dim3 ggrid((N_NODES + 127) / 128, 2);          // 391 x 2
    const size_t BW = (size_t)8 * 32 * 2 * 2 * 32; // uint2 per weight

    detect_kernel<<<1, 32>>>((const unsigned*)edge_idx);
    convert_idx_kernel<<<(N_EDGES + 255) / 256, 256>>>(edge_idx);
    zero_cnt_kernel<<<(N_NODES + 255) / 256, 256>>>();
    hist_kernel<<<(N_EDGES + 255) / 256, 256>>>();
    scan_kernel<<<1, SCAN_T>>>();
    scatter_kernel<<<(N_EDGES + 255) / 256, 256>>>(edge_attr);

    prep_w<<<dim3(16, 32, NWEIGHTS), 32>>>(Wm, pW1, pW2);
    copy_kernel<<<(n4 + 255) / 256, 256>>>((const float4*)x, (float4*)xcur, n4);

    for (int l = 0; l < N_LAYERS; l++) {
        const float* Wel = We + (size_t)l * 3 * HDIM;
        const float* bel = be + (size_t)l * HDIM;
        const float* bml = bmv + (size_t)l * 3 * HDIM;
        const int w0 = l * 3;

        edge_pack<<<MT, 512>>>(xcur, Wel, bel, apk0);

        gemm_bf<<<ggrid, 256>>>(apk0, bpk + (w0+0)*BW, bml,          nullptr, apk1, nullptr, 1);
        gemm_bf<<<ggrid, 256>>>(apk1, bpk + (w0+1)*BW, bml + HDIM,   nullptr, apk0, nullptr, 1);
        gemm_bf<<<ggrid, 256>>>(apk0, bpk + (w0+2)*BW, bml + 2*HDIM, xcur,    apk1, xcur,    2);
    }
    gemm_bf<<<ggrid, 256>>>(apk1, bpk + 9*BW,  pb1, nullptr, apk0, nullptr, 1);
    gemm_bf<<<ggrid, 256>>>(apk0, bpk + 10*BW, pb2, out,     nullptr, nullptr, 0);
}

// round 12
// speedup vs baseline: 1.1725x; 1.1725x over previous
#include <cuda_runtime.h>
#include <cuda_bf16.h>
#include <cstdint>

#define N_NODES 50000
#define N_EDGES 800000
#define HDIM    256
#define N_LAYERS 3
#define NWEIGHTS 11
#define MT 3125                 // 16-row tiles in M (50000/16 exactly)

// ---------------- scratch (no allocation allowed) ----------------
__device__ float g_xcur[N_NODES * HDIM];
__device__ float g_acc [N_NODES * HDIM];
__device__ uint4 g_apk[2][(size_t)MT * 16 * 2 * 32];
// packed split weights: [w][ch(8)][n8(32)][k2(2)][hi/lo][lane(32)] uint2
__device__ uint2 g_bpk[(size_t)NWEIGHTS * 8 * 32 * 2 * 2 * 32];
__device__ int   g_src [N_EDGES];
__device__ int   g_dst [N_EDGES];
__device__ float4 g_easrt[N_EDGES];      // sorted-by-dst: (a0,a1,a2, src-as-int)
__device__ int   g_cnt  [N_NODES];
__device__ int   g_start[N_NODES + 1];
__device__ int   g_fill [N_NODES];
__device__ int   g_is64;

// ---------------- helpers ----------------
__device__ __forceinline__ uint32_t smem_u32(const void* p) {
    uint32_t a;
    asm("{ .reg .u64 t; cvta.to.shared.u64 t, %1; cvt.u32.u64 %0, t; }" : "=r"(a) : "l"(p));
    return a;
}
__device__ __forceinline__ void cpa16(uint32_t dst, const void* src) {
    asm volatile("cp.async.cg.shared.global [%0], [%1], 16;" :: "r"(dst), "l"(src) : "memory");
}
__device__ __forceinline__ uint32_t pk2(float e0, float e1) {
    uint32_t r;
    asm("cvt.rn.bf16x2.f32 %0, %1, %2;" : "=r"(r) : "f"(e1), "f"(e0));
    return r;
}
__device__ __forceinline__ float lo16f(uint32_t r) { return __uint_as_float(r << 16); }
__device__ __forceinline__ float hi16f(uint32_t r) { return __uint_as_float(r & 0xFFFF0000u); }
__device__ __forceinline__ void split2(float v0, float v1, uint32_t& h, uint32_t& l) {
    h = pk2(v0, v1);
    l = pk2(v0 - lo16f(h), v1 - hi16f(h));
}
__device__ __forceinline__ void mma16(float* c, const uint4& a, uint32_t b0, uint32_t b1) {
    asm volatile("mma.sync.aligned.m16n8k16.row.col.f32.bf16.bf16.f32 "
                 "{%0,%1,%2,%3},{%4,%5,%6,%7},{%8,%9},{%0,%1,%2,%3};"
                 : "+f"(c[0]), "+f"(c[1]), "+f"(c[2]), "+f"(c[3])
                 : "r"(a.x), "r"(a.y), "r"(a.z), "r"(a.w), "r"(b0), "r"(b1));
}

// ---------------- index prep ----------------
__global__ void detect_zero_kernel(const unsigned* __restrict__ ei) {
    int i = blockIdx.x * blockDim.x + threadIdx.x;
    if (i < N_NODES) g_cnt[i] = 0;
    if (i == 0) {
        int all0 = 1;
        #pragma unroll 1
        for (int j = 1; j < 128; j += 2) if (ei[j] != 0u) { all0 = 0; break; }
        g_is64 = all0;
    }
}
// convert + histogram fused
__global__ void convert_hist_kernel(const void* __restrict__ ei) {
    int i = blockIdx.x * blockDim.x + threadIdx.x;
    if (i >= N_EDGES) return;
    int s, d;
    if (g_is64) {
        const long long* p = (const long long*)ei;
        s = (int)p[i];
        d = (int)p[N_EDGES + i];
    } else {
        const int* p = (const int*)ei;
        s = p[i];
        d = p[N_EDGES + i];
    }
    g_src[i] = s;
    g_dst[i] = d;
    atomicAdd(&g_cnt[d], 1);
}
#define SCAN_T 1024
#define SCAN_C 49
__global__ __launch_bounds__(SCAN_T) void scan_kernel() {
    __shared__ int ssum[SCAN_T];
    int tid = threadIdx.x;
    int base = tid * SCAN_C;
    int s = 0;
    #pragma unroll 1
    for (int j = 0; j < SCAN_C; j++) {
        int idx = base + j;
        if (idx < N_NODES) s += g_cnt[idx];
    }
    ssum[tid] = s;
    __syncthreads();
    #pragma unroll 1
    for (int off = 1; off < SCAN_T; off <<= 1) {
        int v = (tid >= off) ? ssum[tid - off] : 0;
        __syncthreads();
        ssum[tid] += v;
        __syncthreads();
    }
    int run = ssum[tid] - s;
    #pragma unroll 1
    for (int j = 0; j < SCAN_C; j++) {
        int idx = base + j;
        if (idx < N_NODES) {
            g_start[idx] = run;
            g_fill[idx]  = run;
            run += g_cnt[idx];
        }
    }
    if (tid == 0) g_start[N_NODES] = N_EDGES;
}
__global__ void scatter_kernel(const float* __restrict__ edge_attr) {
    int i = blockIdx.x * blockDim.x + threadIdx.x;
    if (i >= N_EDGES) return;
    int d = g_dst[i];
    int pos = atomicAdd(&g_fill[d], 1);
    float a0 = __ldg(&edge_attr[i * 3 + 0]);
    float a1 = __ldg(&edge_attr[i * 3 + 1]);
    float a2 = __ldg(&edge_attr[i * 3 + 2]);
    g_easrt[pos] = make_float4(a0, a1, a2, __int_as_float(g_src[i]));
}

// ---------------- packing ----------------
__global__ __launch_bounds__(512) void split_kernel(const float* __restrict__ src, uint4* __restrict__ dst) {
    int mt = blockIdx.x;
    int k16 = threadIdx.x >> 5, lane = threadIdx.x & 31;
    int g = lane >> 2, t = lane & 3;
    const float* r0 = src + (size_t)(mt * 16 + g) * HDIM + k16 * 16 + t * 2;
    const float* r1 = r0 + 8 * HDIM;
    float2 v00 = *(const float2*)r0, v01 = *(const float2*)(r0 + 8);
    float2 v10 = *(const float2*)r1, v11 = *(const float2*)(r1 + 8);
    uint4 h, l;
    split2(v00.x, v00.y, h.x, l.x);
    split2(v10.x, v10.y, h.y, l.y);
    split2(v01.x, v01.y, h.z, l.z);
    split2(v11.x, v11.y, h.w, l.w);
    size_t o = ((size_t)(mt * 16 + k16) * 2) * 32 + lane;
    dst[o] = h;
    dst[o + 32] = l;
}
__global__ void prep_w(const float* __restrict__ Wm, const float* __restrict__ pW1,
                       const float* __restrict__ pW2) {
    int w = blockIdx.z, n8 = blockIdx.y, k16 = blockIdx.x;
    int lane = threadIdx.x;
    const float* src = (w < 9) ? (Wm + (size_t)w * HDIM * HDIM) : ((w == 9) ? pW1 : pW2);
    int g = lane >> 2, t = lane & 3;
    int n = n8 * 8 + g;
    int kb = k16 * 16 + t * 2;
    float v0 = src[(size_t)kb * HDIM + n],       v1 = src[(size_t)(kb + 1) * HDIM + n];
    float w0 = src[(size_t)(kb + 8) * HDIM + n], w1 = src[(size_t)(kb + 9) * HDIM + n];
    uint2 hh, ll;
    split2(v0, v1, hh.x, ll.x);
    split2(w0, w1, hh.y, ll.y);
    int ch = k16 >> 1, k2 = k16 & 1;
    size_t o = ((((size_t)w * 8 + ch) * 32 + n8) * 2 + k2) * 2 * 32 + lane;
    g_bpk[o] = hh;
    g_bpk[o + 32] = ll;
}

// ---------------- CSR edge phase: warp per node, register accumulation ----------------
__global__ __launch_bounds__(256) void edge_csr(
    const float* __restrict__ x, float* __restrict__ acc,
    const float* __restrict__ We, const float* __restrict__ be)
{
    int w = blockIdx.x * 8 + (threadIdx.x >> 5);
    if (w >= N_NODES) return;
    int lane = threadIdx.x & 31;
    int h = lane * 8;

    float w0[8], w1[8], w2[8], bb[8];
    #pragma unroll
    for (int j = 0; j < 8; j++) {
        w0[j] = __ldg(We + h + j);
        w1[j] = __ldg(We + HDIM + h + j);
        w2[j] = __ldg(We + 2 * HDIM + h + j);
        bb[j] = __ldg(be + h + j);
    }

    float c[8];
    {
        const float4* xr = (const float4*)(x + (size_t)w * HDIM + h);
        float4 v0 = __ldg(xr), v1 = __ldg(xr + 1);
        c[0] = v0.x; c[1] = v0.y; c[2] = v0.z; c[3] = v0.w;
        c[4] = v1.x; c[5] = v1.y; c[6] = v1.z; c[7] = v1.w;
    }

    int s0 = g_start[w], s1 = g_start[w + 1];
    #pragma unroll 4
    for (int j = s0; j < s1; j++) {
        float4 ea = __ldg(&g_easrt[j]);
        int src = __float_as_int(ea.w);
        const float4* xs = (const float4*)(x + (size_t)src * HDIM + h);
        float4 v0 = __ldg(xs), v1 = __ldg(xs + 1);
        float xv[8] = {v0.x, v0.y, v0.z, v0.w, v1.x, v1.y, v1.z, v1.w};
        #pragma unroll
        for (int k = 0; k < 8; k++) {
            float e = fmaf(ea.x, w0[k], fmaf(ea.y, w1[k], fmaf(ea.z, w2[k], bb[k])));
            c[k] += fmaxf(xv[k] + e, 0.f);
        }
    }

    float4* ar = (float4*)(acc + (size_t)w * HDIM + h);
    ar[0] = make_float4(c[0], c[1], c[2], c[3]);
    ar[1] = make_float4(c[4], c[5], c[6], c[7]);
}

// ---------------- bf16-split mma GEMM (round-7 layout, 3-stage pipeline) ----------------
__global__ __launch_bounds__(256, 2) void gemm_bf(
    const uint4* __restrict__ Apk, const uint2* __restrict__ Bpk,
    const float* __restrict__ bias, float* __restrict__ Cf, uint4* __restrict__ Opk,
    const float* __restrict__ res, int mode)
{
    __shared__ uint2 sb[3][2048];           // 3 x 16KB B staging = 48KB
    const uint32_t sbase = smem_u32(sb);
    const int tid  = threadIdx.x;
    const int lane = tid & 31;
    const int warp = tid >> 5;
    const int g = lane >> 2, t = lane & 3;
    const int wm = warp & 3;
    const int wn = warp >> 2;
    const int bm = blockIdx.x * 128;
    const int bn = blockIdx.y * 128;
    const int bn8 = bn >> 3;

    float acc[2][8][4];
    #pragma unroll
    for (int i = 0; i < 2; i++)
        #pragma unroll
        for (int j = 0; j < 8; j++)
            #pragma unroll
            for (int q = 0; q < 4; q++) acc[i][j][q] = 0.f;

    const int mtA = (bm >> 4) + wm * 2;
    const bool ok0 = (mtA + 0) < MT;
    const bool ok1 = (mtA + 1) < MT;

    auto issue = [&](int ch, int buf) {
        const uint4* src = (const uint4*)(Bpk + ((size_t)ch * 32 + bn8) * 128);
        uint32_t dst = sbase + buf * 16384 + tid * 16;
        #pragma unroll
        for (int i = 0; i < 4; i++) cpa16(dst + i * 4096, src + tid + i * 256);
        asm volatile("cp.async.commit_group;" ::: "memory");
    };
    auto ldA = [&](int k16, uint4 fr[2][2]) {
        #pragma unroll
        for (int mi = 0; mi < 2; mi++) {
            bool ok = mi ? ok1 : ok0;
            size_t o = ((size_t)((mtA + mi) * 16 + k16) * 2) * 32 + lane;
            if (ok) {
                fr[mi][0] = __ldg(Apk + o);
                fr[mi][1] = __ldg(Apk + o + 32);
            } else {
                fr[mi][0] = make_uint4(0, 0, 0, 0);
                fr[mi][1] = make_uint4(0, 0, 0, 0);
            }
        }
    };

    issue(0, 0);
    issue(1, 1);
    issue(2, 2);

    uint4 af[2][2], an[2][2];
    ldA(0, af);

    #pragma unroll 1
    for (int ch = 0; ch < 8; ch++) {
        const int buf = ch % 3;
        if (ch == 7)      asm volatile("cp.async.wait_group 0;" ::: "memory");
        else if (ch == 6) asm volatile("cp.async.wait_group 1;" ::: "memory");
        else              asm volatile("cp.async.wait_group 2;" ::: "memory");
        __syncthreads();

        #pragma unroll
        for (int k2 = 0; k2 < 2; k2++) {
            const int k16 = ch * 2 + k2;
            if (k16 < 15) ldA(k16 + 1, an);
            const uint2* bs = sb[buf];
            uint2 bh[8];
            #pragma unroll
            for (int ni = 0; ni < 8; ni++)
                bh[ni] = bs[(wn * 8 + ni) * 128 + k2 * 64 + lane];
            #pragma unroll
            for (int mi = 0; mi < 2; mi++)
                #pragma unroll
                for (int ni = 0; ni < 8; ni++) {
                    mma16(acc[mi][ni], af[mi][0], bh[ni].x, bh[ni].y);
                    mma16(acc[mi][ni], af[mi][1], bh[ni].x, bh[ni].y);
                }
            uint2 bl[8];
            #pragma unroll
            for (int ni = 0; ni < 8; ni++)
                bl[ni] = bs[(wn * 8 + ni) * 128 + k2 * 64 + 32 + lane];
            #pragma unroll
            for (int mi = 0; mi < 2; mi++)
                #pragma unroll
                for (int ni = 0; ni < 8; ni++)
                    mma16(acc[mi][ni], af[mi][0], bl[ni].x, bl[ni].y);
            if (k16 < 15) {
                #pragma unroll
                for (int mi = 0; mi < 2; mi++) {
                    af[mi][0] = an[mi][0];
                    af[mi][1] = an[mi][1];
                }
            }
        }
        __syncthreads();
        if (ch + 3 < 8) issue(ch + 3, buf);
    }

    #pragma unroll
    for (int ni = 0; ni < 8; ni++) {
        int col = bn + wn * 64 + ni * 8 + t * 2;
        float2 bb = *(const float2*)(bias + col);
        #pragma unroll
        for (int mi = 0; mi < 2; mi++) {
            float* c = acc[mi][ni];
            c[0] += bb.x; c[1] += bb.y; c[2] += bb.x; c[3] += bb.y;
            if (mode >= 1) {
                c[0] = fmaxf(c[0], 0.f); c[1] = fmaxf(c[1], 0.f);
                c[2] = fmaxf(c[2], 0.f); c[3] = fmaxf(c[3], 0.f);
            }
            if (mode == 2) {
                bool ok = mi ? ok1 : ok0;
                if (ok) {
                    int row0 = bm + wm * 32 + mi * 16 + g;
                    float2 r0 = *(const float2*)(res + (size_t)row0 * HDIM + col);
                    float2 r1 = *(const float2*)(res + (size_t)(row0 + 8) * HDIM + col);
                    c[0] += r0.x; c[1] += r0.y; c[2] += r1.x; c[3] += r1.y;
                }
            }
        }
    }
    if (Cf) {
        #pragma unroll
        for (int mi = 0; mi < 2; mi++) {
            bool ok = mi ? ok1 : ok0;
            if (!ok) continue;
            int row0 = bm + wm * 32 + mi * 16 + g;
            #pragma unroll
            for (int ni = 0; ni < 8; ni++) {
                int col = bn + wn * 64 + ni * 8 + t * 2;
                float* c = acc[mi][ni];
                *(float2*)(Cf + (size_t)row0 * HDIM + col)       = make_float2(c[0], c[1]);
                *(float2*)(Cf + (size_t)(row0 + 8) * HDIM + col) = make_float2(c[2], c[3]);
            }
        }
    }
    if (Opk) {
        #pragma unroll
        for (int mi = 0; mi < 2; mi++) {
            bool ok = mi ? ok1 : ok0;
            if (!ok) continue;
            int mt = mtA + mi;
            #pragma unroll
            for (int nip = 0; nip < 4; nip++) {
                float* c0 = acc[mi][nip * 2];
                float* c1 = acc[mi][nip * 2 + 1];
                uint4 h, l;
                split2(c0[0], c0[1], h.x, l.x);
                split2(c0[2], c0[3], h.y, l.y);
                split2(c1[0], c1[1], h.z, l.z);
                split2(c1[2], c1[3], h.w, l.w);
                int k16o = (bn + wn * 64 + nip * 16) >> 4;
                size_t o = ((size_t)(mt * 16 + k16o) * 2) * 32 + lane;
                Opk[o] = h;
                Opk[o + 32] = l;
            }
        }
    }
}

// ---------------- launch ----------------
extern "C" void kernel_launch(void* const* d_in, const int* in_sizes, int n_in,
                              void* d_out, int out_size)
{
    const float* x         = (const float*)d_in[0];
    const void*  edge_idx  = d_in[1];
    const float* edge_attr = (const float*)d_in[2];
    const float* We        = (const float*)d_in[3];
    const float* be        = (const float*)d_in[4];
    const float* Wm        = (const float*)d_in[5];
    const float* bmv       = (const float*)d_in[6];
    const float* pW1       = (const float*)d_in[7];
    const float* pb1       = (const float*)d_in[8];
    const float* pW2       = (const float*)d_in[9];
    const float* pb2       = (const float*)d_in[10];
    float* out             = (float*)d_out;

    float *xcur, *acc;
    uint4 *apk;
    uint2 *bpk;
    cudaGetSymbolAddress((void**)&xcur, g_xcur);
    cudaGetSymbolAddress((void**)&acc,  g_acc);
    cudaGetSymbolAddress((void**)&apk,  g_apk);
    cudaGetSymbolAddress((void**)&bpk,  g_bpk);
    uint4* apk0 = apk;
    uint4* apk1 = apk + (size_t)MT * 16 * 2 * 32;

    dim3 ggrid((N_NODES + 127) / 128, 2);          // 391 x 2
    const size_t BW = (size_t)8 * 32 * 2 * 2 * 32; // uint2 per weight

    detect_zero_kernel<<<(N_NODES + 255) / 256, 256>>>((const unsigned*)edge_idx);
    convert_hist_kernel<<<(N_EDGES + 255) / 256, 256>>>(edge_idx);
    scan_kernel<<<1, SCAN_T>>>();
    scatter_kernel<<<(N_EDGES + 255) / 256, 256>>>(edge_attr);
    prep_w<<<dim3(16, 32, NWEIGHTS), 32>>>(Wm, pW1, pW2);

    for (int l = 0; l < N_LAYERS; l++) {
        const float* Wel = We + (size_t)l * 3 * HDIM;
        const float* bel = be + (size_t)l * HDIM;
        const float* bml = bmv + (size_t)l * 3 * HDIM;
        const int w0 = l * 3;
        const float* xin = (l == 0) ? x : xcur;    // layer 0 reads the input directly

        edge_csr<<<(N_NODES + 7) / 8, 256>>>(xin, acc, Wel, bel);
        split_kernel<<<MT, 512>>>(acc, apk0);

        gemm_bf<<<ggrid, 256>>>(apk0, bpk + (w0+0)*BW, bml,          nullptr, apk1, nullptr, 1);
        gemm_bf<<<ggrid, 256>>>(apk1, bpk + (w0+1)*BW, bml + HDIM,   nullptr, apk0, nullptr, 1);
        gemm_bf<<<ggrid, 256>>>(apk0, bpk + (w0+2)*BW, bml + 2*HDIM, xcur,    apk1, xin,     2);
    }
    gemm_bf<<<ggrid, 256>>>(apk1, bpk + 9*BW,  pb1, nullptr, apk0, nullptr, 1);
    gemm_bf<<<ggrid, 256>>>(apk0, bpk + 10*BW, pb2, out,     nullptr, nullptr, 0);
}

// round 13
// speedup vs baseline: 1.2037x; 1.0266x over previous
#include <cuda_runtime.h>
#include <cuda_bf16.h>
#include <cstdint>

#define N_NODES 50000
#define N_EDGES 800000
#define HDIM    256
#define N_LAYERS 3
#define NWEIGHTS 11
#define MT 3125                 // 16-row tiles in M (50000/16 exactly)

// ---------------- scratch (no allocation allowed) ----------------
__device__ float g_xcur[N_NODES * HDIM];
__device__ uint4 g_apk[2][(size_t)MT * 16 * 2 * 32];
// packed split weights: [w][ch(8)][n8(32)][k2(2)][hi/lo][lane(32)] uint2
__device__ uint2 g_bpk[(size_t)NWEIGHTS * 8 * 32 * 2 * 2 * 32];
__device__ int   g_src [N_EDGES];
__device__ int   g_dst [N_EDGES];
__device__ float4 g_easrt[N_EDGES];      // sorted-by-dst: (a0,a1,a2, src-as-int)
__device__ int   g_cnt  [N_NODES];
__device__ int   g_start[N_NODES + 1];
__device__ int   g_fill [N_NODES];
__device__ int   g_is64;

// ---------------- helpers ----------------
__device__ __forceinline__ uint32_t smem_u32(const void* p) {
    uint32_t a;
    asm("{ .reg .u64 t; cvta.to.shared.u64 t, %1; cvt.u32.u64 %0, t; }" : "=r"(a) : "l"(p));
    return a;
}
__device__ __forceinline__ void cpa16(uint32_t dst, const void* src) {
    asm volatile("cp.async.cg.shared.global [%0], [%1], 16;" :: "r"(dst), "l"(src) : "memory");
}
__device__ __forceinline__ uint32_t pk2(float e0, float e1) {
    uint32_t r;
    asm("cvt.rn.bf16x2.f32 %0, %1, %2;" : "=r"(r) : "f"(e1), "f"(e0));
    return r;
}
__device__ __forceinline__ float lo16f(uint32_t r) { return __uint_as_float(r << 16); }
__device__ __forceinline__ float hi16f(uint32_t r) { return __uint_as_float(r & 0xFFFF0000u); }
__device__ __forceinline__ void split2(float v0, float v1, uint32_t& h, uint32_t& l) {
    h = pk2(v0, v1);
    l = pk2(v0 - lo16f(h), v1 - hi16f(h));
}
__device__ __forceinline__ void mma16(float* c, const uint4& a, uint32_t b0, uint32_t b1) {
    asm volatile("mma.sync.aligned.m16n8k16.row.col.f32.bf16.bf16.f32 "
                 "{%0,%1,%2,%3},{%4,%5,%6,%7},{%8,%9},{%0,%1,%2,%3};"
                 : "+f"(c[0]), "+f"(c[1]), "+f"(c[2]), "+f"(c[3])
                 : "r"(a.x), "r"(a.y), "r"(a.z), "r"(a.w), "r"(b0), "r"(b1));
}

// ---------------- index prep ----------------
__global__ void detect_zero_kernel(const unsigned* __restrict__ ei) {
    int i = blockIdx.x * blockDim.x + threadIdx.x;
    if (i < N_NODES) g_cnt[i] = 0;
    if (i == 0) {
        int all0 = 1;
        #pragma unroll 1
        for (int j = 1; j < 128; j += 2) if (ei[j] != 0u) { all0 = 0; break; }
        g_is64 = all0;
    }
}
__global__ void convert_hist_kernel(const void* __restrict__ ei) {
    int i = blockIdx.x * blockDim.x + threadIdx.x;
    if (i >= N_EDGES) return;
    int s, d;
    if (g_is64) {
        const long long* p = (const long long*)ei;
        s = (int)p[i];
        d = (int)p[N_EDGES + i];
    } else {
        const int* p = (const int*)ei;
        s = p[i];
        d = p[N_EDGES + i];
    }
    g_src[i] = s;
    g_dst[i] = d;
    atomicAdd(&g_cnt[d], 1);
}
#define SCAN_T 1024
#define SCAN_C 49
__global__ __launch_bounds__(SCAN_T) void scan_kernel() {
    __shared__ int ssum[SCAN_T];
    int tid = threadIdx.x;
    int base = tid * SCAN_C;
    int s = 0;
    #pragma unroll 1
    for (int j = 0; j < SCAN_C; j++) {
        int idx = base + j;
        if (idx < N_NODES) s += g_cnt[idx];
    }
    ssum[tid] = s;
    __syncthreads();
    #pragma unroll 1
    for (int off = 1; off < SCAN_T; off <<= 1) {
        int v = (tid >= off) ? ssum[tid - off] : 0;
        __syncthreads();
        ssum[tid] += v;
        __syncthreads();
    }
    int run = ssum[tid] - s;
    #pragma unroll 1
    for (int j = 0; j < SCAN_C; j++) {
        int idx = base + j;
        if (idx < N_NODES) {
            g_start[idx] = run;
            g_fill[idx]  = run;
            run += g_cnt[idx];
        }
    }
    if (tid == 0) g_start[N_NODES] = N_EDGES;
}
__global__ void scatter_kernel(const float* __restrict__ edge_attr) {
    int i = blockIdx.x * blockDim.x + threadIdx.x;
    if (i >= N_EDGES) return;
    int d = g_dst[i];
    int pos = atomicAdd(&g_fill[d], 1);
    float a0 = __ldg(&edge_attr[i * 3 + 0]);
    float a1 = __ldg(&edge_attr[i * 3 + 1]);
    float a2 = __ldg(&edge_attr[i * 3 + 2]);
    g_easrt[pos] = make_float4(a0, a1, a2, __int_as_float(g_src[i]));
}

// ---------------- weight packing ----------------
__global__ void prep_w(const float* __restrict__ Wm, const float* __restrict__ pW1,
                       const float* __restrict__ pW2) {
    int w = blockIdx.z, n8 = blockIdx.y, k16 = blockIdx.x;
    int lane = threadIdx.x;
    const float* src = (w < 9) ? (Wm + (size_t)w * HDIM * HDIM) : ((w == 9) ? pW1 : pW2);
    int g = lane >> 2, t = lane & 3;
    int n = n8 * 8 + g;
    int kb = k16 * 16 + t * 2;
    float v0 = src[(size_t)kb * HDIM + n],       v1 = src[(size_t)(kb + 1) * HDIM + n];
    float w0 = src[(size_t)(kb + 8) * HDIM + n], w1 = src[(size_t)(kb + 9) * HDIM + n];
    uint2 hh, ll;
    split2(v0, v1, hh.x, ll.x);
    split2(w0, w1, hh.y, ll.y);
    int ch = k16 >> 1, k2 = k16 & 1;
    size_t o = ((((size_t)w * 8 + ch) * 32 + n8) * 2 + k2) * 2 * 32 + lane;
    g_bpk[o] = hh;
    g_bpk[o + 32] = ll;
}

// ---------------- fused edge phase + bf16 split/pack (unroll-2 edge loop) ----------------
__global__ __launch_bounds__(512) void edge_pack(
    const float* __restrict__ x,
    const float* __restrict__ We, const float* __restrict__ be,
    uint4* __restrict__ dst)
{
    __shared__ float s[16][HDIM + 2];
    int wid = threadIdx.x >> 5, lane = threadIdx.x & 31;
    int node = blockIdx.x * 16 + wid;
    int h = lane * 8;

    float w0[8], w1[8], w2[8], bb[8];
    #pragma unroll
    for (int j = 0; j < 8; j++) {
        w0[j] = __ldg(We + h + j);
        w1[j] = __ldg(We + HDIM + h + j);
        w2[j] = __ldg(We + 2 * HDIM + h + j);
        bb[j] = __ldg(be + h + j);
    }

    float c[8];
    {
        const float4* xr = (const float4*)(x + (size_t)node * HDIM + h);
        float4 v0 = __ldg(xr), v1 = __ldg(xr + 1);
        c[0] = v0.x; c[1] = v0.y; c[2] = v0.z; c[3] = v0.w;
        c[4] = v1.x; c[5] = v1.y; c[6] = v1.z; c[7] = v1.w;
    }
    int s0 = g_start[node], s1 = g_start[node + 1];
    #pragma unroll 2
    for (int j = s0; j < s1; j++) {
        float4 ea = __ldg(&g_easrt[j]);
        int src = __float_as_int(ea.w);
        const float4* xs = (const float4*)(x + (size_t)src * HDIM + h);
        float4 v0 = __ldg(xs), v1 = __ldg(xs + 1);
        float xv[8] = {v0.x, v0.y, v0.z, v0.w, v1.x, v1.y, v1.z, v1.w};
        #pragma unroll
        for (int k = 0; k < 8; k++) {
            float e = fmaf(ea.x, w0[k], fmaf(ea.y, w1[k], fmaf(ea.z, w2[k], bb[k])));
            c[k] += fmaxf(xv[k] + e, 0.f);
        }
    }
    #pragma unroll
    for (int j = 0; j < 8; j++) s[wid][h + j] = c[j];
    __syncthreads();

    // repack: warp wid handles k16 group wid
    int g = lane >> 2, t = lane & 3;
    const float* r0 = &s[g][wid * 16 + t * 2];
    const float* r1 = &s[g + 8][wid * 16 + t * 2];
    float2 v00 = make_float2(r0[0], r0[1]), v01 = make_float2(r0[8], r0[9]);
    float2 v10 = make_float2(r1[0], r1[1]), v11 = make_float2(r1[8], r1[9]);
    uint4 hh, ll;
    split2(v00.x, v00.y, hh.x, ll.x);
    split2(v10.x, v10.y, hh.y, ll.y);
    split2(v01.x, v01.y, hh.z, ll.z);
    split2(v11.x, v11.y, hh.w, ll.w);
    size_t o = ((size_t)(blockIdx.x * 16 + wid) * 2) * 32 + lane;
    dst[o] = hh;
    dst[o + 32] = ll;
}

// ---------------- bf16-split mma GEMM (round-7 layout, 3-stage pipeline) ----------------
__global__ __launch_bounds__(256, 2) void gemm_bf(
    const uint4* __restrict__ Apk, const uint2* __restrict__ Bpk,
    const float* __restrict__ bias, float* __restrict__ Cf, uint4* __restrict__ Opk,
    const float* __restrict__ res, int mode)
{
    __shared__ uint2 sb[3][2048];           // 3 x 16KB B staging = 48KB
    const uint32_t sbase = smem_u32(sb);
    const int tid  = threadIdx.x;
    const int lane = tid & 31;
    const int warp = tid >> 5;
    const int g = lane >> 2, t = lane & 3;
    const int wm = warp & 3;
    const int wn = warp >> 2;
    const int bm = blockIdx.x * 128;
    const int bn = blockIdx.y * 128;
    const int bn8 = bn >> 3;

    float acc[2][8][4];
    #pragma unroll
    for (int i = 0; i < 2; i++)
        #pragma unroll
        for (int j = 0; j < 8; j++)
            #pragma unroll
            for (int q = 0; q < 4; q++) acc[i][j][q] = 0.f;

    const int mtA = (bm >> 4) + wm * 2;
    const bool ok0 = (mtA + 0) < MT;
    const bool ok1 = (mtA + 1) < MT;

    auto issue = [&](int ch, int buf) {
        const uint4* src = (const uint4*)(Bpk + ((size_t)ch * 32 + bn8) * 128);
        uint32_t dst = sbase + buf * 16384 + tid * 16;
        #pragma unroll
        for (int i = 0; i < 4; i++) cpa16(dst + i * 4096, src + tid + i * 256);
        asm volatile("cp.async.commit_group;" ::: "memory");
    };
    auto ldA = [&](int k16, uint4 fr[2][2]) {
        #pragma unroll
        for (int mi = 0; mi < 2; mi++) {
            bool ok = mi ? ok1 : ok0;
            size_t o = ((size_t)((mtA + mi) * 16 + k16) * 2) * 32 + lane;
            if (ok) {
                fr[mi][0] = __ldg(Apk + o);
                fr[mi][1] = __ldg(Apk + o + 32);
            } else {
                fr[mi][0] = make_uint4(0, 0, 0, 0);
                fr[mi][1] = make_uint4(0, 0, 0, 0);
            }
        }
    };

    issue(0, 0);
    issue(1, 1);
    issue(2, 2);

    uint4 af[2][2], an[2][2];
    ldA(0, af);

    #pragma unroll 1
    for (int ch = 0; ch < 8; ch++) {
        const int buf = ch % 3;
        if (ch == 7)      asm volatile("cp.async.wait_group 0;" ::: "memory");
        else if (ch == 6) asm volatile("cp.async.wait_group 1;" ::: "memory");
        else              asm volatile("cp.async.wait_group 2;" ::: "memory");
        __syncthreads();

        #pragma unroll
        for (int k2 = 0; k2 < 2; k2++) {
            const int k16 = ch * 2 + k2;
            if (k16 < 15) ldA(k16 + 1, an);
            const uint2* bs = sb[buf];
            uint2 bh[8];
            #pragma unroll
            for (int ni = 0; ni < 8; ni++)
                bh[ni] = bs[(wn * 8 + ni) * 128 + k2 * 64 + lane];
            #pragma unroll
            for (int mi = 0; mi < 2; mi++)
                #pragma unroll
                for (int ni = 0; ni < 8; ni++) {
                    mma16(acc[mi][ni], af[mi][0], bh[ni].x, bh[ni].y);
                    mma16(acc[mi][ni], af[mi][1], bh[ni].x, bh[ni].y);
                }
            uint2 bl[8];
            #pragma unroll
            for (int ni = 0; ni < 8; ni++)
                bl[ni] = bs[(wn * 8 + ni) * 128 + k2 * 64 + 32 + lane];
            #pragma unroll
            for (int mi = 0; mi < 2; mi++)
                #pragma unroll
                for (int ni = 0; ni < 8; ni++)
                    mma16(acc[mi][ni], af[mi][0], bl[ni].x, bl[ni].y);
            if (k16 < 15) {
                #pragma unroll
                for (int mi = 0; mi < 2; mi++) {
                    af[mi][0] = an[mi][0];
                    af[mi][1] = an[mi][1];
                }
            }
        }
        __syncthreads();
        if (ch + 3 < 8) issue(ch + 3, buf);
    }

    #pragma unroll
    for (int ni = 0; ni < 8; ni++) {
        int col = bn + wn * 64 + ni * 8 + t * 2;
        float2 bb = *(const float2*)(bias + col);
        #pragma unroll
        for (int mi = 0; mi < 2; mi++) {
            float* c = acc[mi][ni];
            c[0] += bb.x; c[1] += bb.y; c[2] += bb.x; c[3] += bb.y;
            if (mode >= 1) {
                c[0] = fmaxf(c[0], 0.f); c[1] = fmaxf(c[1], 0.f);
                c[2] = fmaxf(c[2], 0.f); c[3] = fmaxf(c[3], 0.f);
            }
            if (mode == 2) {
                bool ok = mi ? ok1 : ok0;
                if (ok) {
                    int row0 = bm + wm * 32 + mi * 16 + g;
                    float2 r0 = *(const float2*)(res + (size_t)row0 * HDIM + col);
                    float2 r1 = *(const float2*)(res + (size_t)(row0 + 8) * HDIM + col);
                    c[0] += r0.x; c[1] += r0.y; c[2] += r1.x; c[3] += r1.y;
                }
            }
        }
    }
    if (Cf) {
        #pragma unroll
        for (int mi = 0; mi < 2; mi++) {
            bool ok = mi ? ok1 : ok0;
            if (!ok) continue;
            int row0 = bm + wm * 32 + mi * 16 + g;
            #pragma unroll
            for (int ni = 0; ni < 8; ni++) {
                int col = bn + wn * 64 + ni * 8 + t * 2;
                float* c = acc[mi][ni];
                *(float2*)(Cf + (size_t)row0 * HDIM + col)       = make_float2(c[0], c[1]);
                *(float2*)(Cf + (size_t)(row0 + 8) * HDIM + col) = make_float2(c[2], c[3]);
            }
        }
    }
    if (Opk) {
        #pragma unroll
        for (int mi = 0; mi < 2; mi++) {
            bool ok = mi ? ok1 : ok0;
            if (!ok) continue;
            int mt = mtA + mi;
            #pragma unroll
            for (int nip = 0; nip < 4; nip++) {
                float* c0 = acc[mi][nip * 2];
                float* c1 = acc[mi][nip * 2 + 1];
                uint4 h, l;
                split2(c0[0], c0[1], h.x, l.x);
                split2(c0[2], c0[3], h.y, l.y);
                split2(c1[0], c1[1], h.z, l.z);
                split2(c1[2], c1[3], h.w, l.w);
                int k16o = (bn + wn * 64 + nip * 16) >> 4;
                size_t o = ((size_t)(mt * 16 + k16o) * 2) * 32 + lane;
                Opk[o] = h;
                Opk[o + 32] = l;
            }
        }
    }
}

// ---------------- launch ----------------
extern "C" void kernel_launch(void* const* d_in, const int* in_sizes, int n_in,
                              void* d_out, int out_size)
{
    const float* x         = (const float*)d_in[0];
    const void*  edge_idx  = d_in[1];
    const float* edge_attr = (const float*)d_in[2];
    const float* We        = (const float*)d_in[3];
    const float* be        = (const float*)d_in[4];
    const float* Wm        = (const float*)d_in[5];
    const float* bmv       = (const float*)d_in[6];
    const float* pW1       = (const float*)d_in[7];
    const float* pb1       = (const float*)d_in[8];
    const float* pW2       = (const float*)d_in[9];
    const float* pb2       = (const float*)d_in[10];
    float* out             = (float*)d_out;

    float *xcur;
    uint4 *apk;
    uint2 *bpk;
    cudaGetSymbolAddress((void**)&xcur, g_xcur);
    cudaGetSymbolAddress((void**)&apk,  g_apk);
    cudaGetSymbolAddress((void**)&bpk,  g_bpk);
    uint4* apk0 = apk;
    uint4* apk1 = apk + (size_t)MT * 16 * 2 * 32;

    dim3 ggrid((N_NODES + 127) / 128, 2);          // 391 x 2
    const size_t BW = (size_t)8 * 32 * 2 * 2 * 32; // uint2 per weight

    detect_zero_kernel<<<(N_NODES + 255) / 256, 256>>>((const unsigned*)edge_idx);
    convert_hist_kernel<<<(N_EDGES + 255) / 256, 256>>>(edge_idx);
    scan_kernel<<<1, SCAN_T>>>();
    scatter_kernel<<<(N_EDGES + 255) / 256, 256>>>(edge_attr);
    prep_w<<<dim3(16, 32, NWEIGHTS), 32>>>(Wm, pW1, pW2);

    for (int l = 0; l < N_LAYERS; l++) {
        const float* Wel = We + (size_t)l * 3 * HDIM;
        const float* bel = be + (size_t)l * HDIM;
        const float* bml = bmv + (size_t)l * 3 * HDIM;
        const int w0 = l * 3;
        const float* xin = (l == 0) ? x : xcur;    // layer 0 reads the input directly

        edge_pack<<<MT, 512>>>(xin, Wel, bel, apk0);

        gemm_bf<<<ggrid, 256>>>(apk0, bpk + (w0+0)*BW, bml,          nullptr, apk1, nullptr, 1);
        gemm_bf<<<ggrid, 256>>>(apk1, bpk + (w0+1)*BW, bml + HDIM,   nullptr, apk0, nullptr, 1);
        gemm_bf<<<ggrid, 256>>>(apk0, bpk + (w0+2)*BW, bml + 2*HDIM, xcur,    apk1, xin,     2);
    }
    gemm_bf<<<ggrid, 256>>>(apk1, bpk + 9*BW,  pb1, nullptr, apk0, nullptr, 1);
    gemm_bf<<<ggrid, 256>>>(apk0, bpk + 10*BW, pb2, out,     nullptr, nullptr, 0);
}

// round 14
// speedup vs baseline: 1.2188x; 1.0126x over previous
#include <cuda_runtime.h>
#include <cuda_bf16.h>
#include <cstdint>

#define N_NODES 50000
#define N_EDGES 800000
#define HDIM    256
#define N_LAYERS 3
#define NWEIGHTS 11
#define MT 3125                 // 16-row tiles in M (50000/16 exactly)

// ---------------- scratch (no allocation allowed) ----------------
__device__ float g_xcur[N_NODES * HDIM];
__device__ uint4 g_apk[2][(size_t)MT * 16 * 2 * 32];
// packed split weights: [w][ch(8)][n8(32)][k2(2)][hi/lo][lane(32)] uint2
__device__ uint2 g_bpk[(size_t)NWEIGHTS * 8 * 32 * 2 * 2 * 32];
__device__ int   g_src [N_EDGES];
__device__ int   g_dst [N_EDGES];
__device__ float4 g_easrt[N_EDGES];      // sorted-by-dst: (a0,a1,a2, src-as-int)
__device__ int   g_cnt  [N_NODES];
__device__ int   g_start[N_NODES + 1];
__device__ int   g_fill [N_NODES];
__device__ int   g_is64;

// ---------------- helpers ----------------
__device__ __forceinline__ uint32_t smem_u32(const void* p) {
    uint32_t a;
    asm("{ .reg .u64 t; cvta.to.shared.u64 t, %1; cvt.u32.u64 %0, t; }" : "=r"(a) : "l"(p));
    return a;
}
__device__ __forceinline__ void cpa16(uint32_t dst, const void* src) {
    asm volatile("cp.async.cg.shared.global [%0], [%1], 16;" :: "r"(dst), "l"(src) : "memory");
}
__device__ __forceinline__ uint32_t pk2(float e0, float e1) {
    uint32_t r;
    asm("cvt.rn.bf16x2.f32 %0, %1, %2;" : "=r"(r) : "f"(e1), "f"(e0));
    return r;
}
__device__ __forceinline__ float lo16f(uint32_t r) { return __uint_as_float(r << 16); }
__device__ __forceinline__ float hi16f(uint32_t r) { return __uint_as_float(r & 0xFFFF0000u); }
__device__ __forceinline__ void split2(float v0, float v1, uint32_t& h, uint32_t& l) {
    h = pk2(v0, v1);
    l = pk2(v0 - lo16f(h), v1 - hi16f(h));
}
__device__ __forceinline__ void mma16(float* c, const uint4& a, uint32_t b0, uint32_t b1) {
    asm volatile("mma.sync.aligned.m16n8k16.row.col.f32.bf16.bf16.f32 "
                 "{%0,%1,%2,%3},{%4,%5,%6,%7},{%8,%9},{%0,%1,%2,%3};"
                 : "+f"(c[0]), "+f"(c[1]), "+f"(c[2]), "+f"(c[3])
                 : "r"(a.x), "r"(a.y), "r"(a.z), "r"(a.w), "r"(b0), "r"(b1));
}

// ---------------- index prep ----------------
__global__ void detect_zero_kernel(const unsigned* __restrict__ ei) {
    int i = blockIdx.x * blockDim.x + threadIdx.x;
    if (i < N_NODES) g_cnt[i] = 0;
    if (i == 0) {
        int all0 = 1;
        #pragma unroll 1
        for (int j = 1; j < 128; j += 2) if (ei[j] != 0u) { all0 = 0; break; }
        g_is64 = all0;
    }
}
__global__ void convert_hist_kernel(const void* __restrict__ ei) {
    int i = blockIdx.x * blockDim.x + threadIdx.x;
    if (i >= N_EDGES) return;
    int s, d;
    if (g_is64) {
        const long long* p = (const long long*)ei;
        s = (int)p[i];
        d = (int)p[N_EDGES + i];
    } else {
        const int* p = (const int*)ei;
        s = p[i];
        d = p[N_EDGES + i];
    }
    g_src[i] = s;
    g_dst[i] = d;
    atomicAdd(&g_cnt[d], 1);
}
#define SCAN_T 1024
#define SCAN_C 49
__global__ __launch_bounds__(SCAN_T) void scan_kernel() {
    __shared__ int ssum[SCAN_T];
    int tid = threadIdx.x;
    int base = tid * SCAN_C;
    int s = 0;
    #pragma unroll 1
    for (int j = 0; j < SCAN_C; j++) {
        int idx = base + j;
        if (idx < N_NODES) s += g_cnt[idx];
    }
    ssum[tid] = s;
    __syncthreads();
    #pragma unroll 1
    for (int off = 1; off < SCAN_T; off <<= 1) {
        int v = (tid >= off) ? ssum[tid - off] : 0;
        __syncthreads();
        ssum[tid] += v;
        __syncthreads();
    }
    int run = ssum[tid] - s;
    #pragma unroll 1
    for (int j = 0; j < SCAN_C; j++) {
        int idx = base + j;
        if (idx < N_NODES) {
            g_start[idx] = run;
            g_fill[idx]  = run;
            run += g_cnt[idx];
        }
    }
    if (tid == 0) g_start[N_NODES] = N_EDGES;
}
__global__ void scatter_kernel(const float* __restrict__ edge_attr) {
    int i = blockIdx.x * blockDim.x + threadIdx.x;
    if (i >= N_EDGES) return;
    int d = g_dst[i];
    int pos = atomicAdd(&g_fill[d], 1);
    float a0 = __ldg(&edge_attr[i * 3 + 0]);
    float a1 = __ldg(&edge_attr[i * 3 + 1]);
    float a2 = __ldg(&edge_attr[i * 3 + 2]);
    g_easrt[pos] = make_float4(a0, a1, a2, __int_as_float(g_src[i]));
}

// ---------------- weight packing ----------------
__global__ void prep_w(const float* __restrict__ Wm, const float* __restrict__ pW1,
                       const float* __restrict__ pW2) {
    int w = blockIdx.z, n8 = blockIdx.y, k16 = blockIdx.x;
    int lane = threadIdx.x;
    const float* src = (w < 9) ? (Wm + (size_t)w * HDIM * HDIM) : ((w == 9) ? pW1 : pW2);
    int g = lane >> 2, t = lane & 3;
    int n = n8 * 8 + g;
    int kb = k16 * 16 + t * 2;
    float v0 = src[(size_t)kb * HDIM + n],       v1 = src[(size_t)(kb + 1) * HDIM + n];
    float w0 = src[(size_t)(kb + 8) * HDIM + n], w1 = src[(size_t)(kb + 9) * HDIM + n];
    uint2 hh, ll;
    split2(v0, v1, hh.x, ll.x);
    split2(w0, w1, hh.y, ll.y);
    int ch = k16 >> 1, k2 = k16 & 1;
    size_t o = ((((size_t)w * 8 + ch) * 32 + n8) * 2 + k2) * 2 * 32 + lane;
    g_bpk[o] = hh;
    g_bpk[o + 32] = ll;
}

// ---------------- fused edge phase + bf16 split/pack (unroll-2 edge loop) ----------------
__global__ __launch_bounds__(512) void edge_pack(
    const float* __restrict__ x,
    const float* __restrict__ We, const float* __restrict__ be,
    uint4* __restrict__ dst)
{
    __shared__ float s[16][HDIM + 2];
    int wid = threadIdx.x >> 5, lane = threadIdx.x & 31;
    int node = blockIdx.x * 16 + wid;
    int h = lane * 8;

    float w0[8], w1[8], w2[8], bb[8];
    #pragma unroll
    for (int j = 0; j < 8; j++) {
        w0[j] = __ldg(We + h + j);
        w1[j] = __ldg(We + HDIM + h + j);
        w2[j] = __ldg(We + 2 * HDIM + h + j);
        bb[j] = __ldg(be + h + j);
    }

    float c[8];
    {
        const float4* xr = (const float4*)(x + (size_t)node * HDIM + h);
        float4 v0 = __ldg(xr), v1 = __ldg(xr + 1);
        c[0] = v0.x; c[1] = v0.y; c[2] = v0.z; c[3] = v0.w;
        c[4] = v1.x; c[5] = v1.y; c[6] = v1.z; c[7] = v1.w;
    }
    int s0 = g_start[node], s1 = g_start[node + 1];
    #pragma unroll 2
    for (int j = s0; j < s1; j++) {
        float4 ea = __ldg(&g_easrt[j]);
        int src = __float_as_int(ea.w);
        const float4* xs = (const float4*)(x + (size_t)src * HDIM + h);
        float4 v0 = __ldg(xs), v1 = __ldg(xs + 1);
        float xv[8] = {v0.x, v0.y, v0.z, v0.w, v1.x, v1.y, v1.z, v1.w};
        #pragma unroll
        for (int k = 0; k < 8; k++) {
            float e = fmaf(ea.x, w0[k], fmaf(ea.y, w1[k], fmaf(ea.z, w2[k], bb[k])));
            c[k] += fmaxf(xv[k] + e, 0.f);
        }
    }
    #pragma unroll
    for (int j = 0; j < 8; j++) s[wid][h + j] = c[j];
    __syncthreads();

    // repack: warp wid handles k16 group wid
    int g = lane >> 2, t = lane & 3;
    const float* r0 = &s[g][wid * 16 + t * 2];
    const float* r1 = &s[g + 8][wid * 16 + t * 2];
    float2 v00 = make_float2(r0[0], r0[1]), v01 = make_float2(r0[8], r0[9]);
    float2 v10 = make_float2(r1[0], r1[1]), v11 = make_float2(r1[8], r1[9]);
    uint4 hh, ll;
    split2(v00.x, v00.y, hh.x, ll.x);
    split2(v10.x, v10.y, hh.y, ll.y);
    split2(v01.x, v01.y, hh.z, ll.z);
    split2(v11.x, v11.y, hh.w, ll.w);
    size_t o = ((size_t)(blockIdx.x * 16 + wid) * 2) * 32 + lane;
    dst[o] = hh;
    dst[o + 32] = ll;
}

// ---------------- bf16-split mma GEMM: 4-stage ring, one sync per chunk ----------------
#define GSMEM (4 * 16384)   // 4 x 16KB B staging = 64KB dynamic

__global__ __launch_bounds__(256, 2) void gemm_bf(
    const uint4* __restrict__ Apk, const uint2* __restrict__ Bpk,
    const float* __restrict__ bias, float* __restrict__ Cf, uint4* __restrict__ Opk,
    const float* __restrict__ res, int mode)
{
    extern __shared__ uint2 sbd[];
    const uint32_t sbase = smem_u32(sbd);
    const int tid  = threadIdx.x;
    const int lane = tid & 31;
    const int warp = tid >> 5;
    const int g = lane >> 2, t = lane & 3;
    const int wm = warp & 3;
    const int wn = warp >> 2;
    const int bm = blockIdx.x * 128;
    const int bn = blockIdx.y * 128;
    const int bn8 = bn >> 3;

    float acc[2][8][4];
    #pragma unroll
    for (int i = 0; i < 2; i++)
        #pragma unroll
        for (int j = 0; j < 8; j++)
            #pragma unroll
            for (int q = 0; q < 4; q++) acc[i][j][q] = 0.f;

    const int mtA = (bm >> 4) + wm * 2;
    const bool ok0 = (mtA + 0) < MT;
    const bool ok1 = (mtA + 1) < MT;

    auto issue = [&](int ch, int buf) {
        const uint4* src = (const uint4*)(Bpk + ((size_t)ch * 32 + bn8) * 128);
        uint32_t dst = sbase + buf * 16384 + tid * 16;
        #pragma unroll
        for (int i = 0; i < 4; i++) cpa16(dst + i * 4096, src + tid + i * 256);
        asm volatile("cp.async.commit_group;" ::: "memory");
    };
    auto ldA = [&](int k16, uint4 fr[2][2]) {
        #pragma unroll
        for (int mi = 0; mi < 2; mi++) {
            bool ok = mi ? ok1 : ok0;
            size_t o = ((size_t)((mtA + mi) * 16 + k16) * 2) * 32 + lane;
            if (ok) {
                fr[mi][0] = __ldg(Apk + o);
                fr[mi][1] = __ldg(Apk + o + 32);
            } else {
                fr[mi][0] = make_uint4(0, 0, 0, 0);
                fr[mi][1] = make_uint4(0, 0, 0, 0);
            }
        }
    };

    issue(0, 0);
    issue(1, 1);
    issue(2, 2);

    uint4 af[2][2], an[2][2];
    ldA(0, af);

    #pragma unroll 1
    for (int ch = 0; ch < 8; ch++) {
        const int buf = ch & 3;
        // need group ch complete; allow min(2, 7-ch) groups pending
        if (ch >= 6) {
            if (ch == 6) asm volatile("cp.async.wait_group 1;" ::: "memory");
            else         asm volatile("cp.async.wait_group 0;" ::: "memory");
        } else {
            asm volatile("cp.async.wait_group 2;" ::: "memory");
        }
        __syncthreads();
        // buffer (ch+3)&3 was consumed at iteration ch-1; safe to refill now
        if (ch + 3 < 8) issue(ch + 3, (ch + 3) & 3);

        #pragma unroll
        for (int k2 = 0; k2 < 2; k2++) {
            const int k16 = ch * 2 + k2;
            if (k16 < 15) ldA(k16 + 1, an);
            const uint2* bs = sbd + buf * 2048;
            uint2 bh[8];
            #pragma unroll
            for (int ni = 0; ni < 8; ni++)
                bh[ni] = bs[(wn * 8 + ni) * 128 + k2 * 64 + lane];
            #pragma unroll
            for (int mi = 0; mi < 2; mi++)
                #pragma unroll
                for (int ni = 0; ni < 8; ni++) {
                    mma16(acc[mi][ni], af[mi][0], bh[ni].x, bh[ni].y);
                    mma16(acc[mi][ni], af[mi][1], bh[ni].x, bh[ni].y);
                }
            uint2 bl[8];
            #pragma unroll
            for (int ni = 0; ni < 8; ni++)
                bl[ni] = bs[(wn * 8 + ni) * 128 + k2 * 64 + 32 + lane];
            #pragma unroll
            for (int mi = 0; mi < 2; mi++)
                #pragma unroll
                for (int ni = 0; ni < 8; ni++)
                    mma16(acc[mi][ni], af[mi][0], bl[ni].x, bl[ni].y);
            if (k16 < 15) {
                #pragma unroll
                for (int mi = 0; mi < 2; mi++) {
                    af[mi][0] = an[mi][0];
                    af[mi][1] = an[mi][1];
                }
            }
        }
    }

    #pragma unroll
    for (int ni = 0; ni < 8; ni++) {
        int col = bn + wn * 64 + ni * 8 + t * 2;
        float2 bb = *(const float2*)(bias + col);
        #pragma unroll
        for (int mi = 0; mi < 2; mi++) {
            float* c = acc[mi][ni];
            c[0] += bb.x; c[1] += bb.y; c[2] += bb.x; c[3] += bb.y;
            if (mode >= 1) {
                c[0] = fmaxf(c[0], 0.f); c[1] = fmaxf(c[1], 0.f);
                c[2] = fmaxf(c[2], 0.f); c[3] = fmaxf(c[3], 0.f);
            }
            if (mode == 2) {
                bool ok = mi ? ok1 : ok0;
                if (ok) {
                    int row0 = bm + wm * 32 + mi * 16 + g;
                    float2 r0 = *(const float2*)(res + (size_t)row0 * HDIM + col);
                    float2 r1 = *(const float2*)(res + (size_t)(row0 + 8) * HDIM + col);
                    c[0] += r0.x; c[1] += r0.y; c[2] += r1.x; c[3] += r1.y;
                }
            }
        }
    }
    if (Cf) {
        #pragma unroll
        for (int mi = 0; mi < 2; mi++) {
            bool ok = mi ? ok1 : ok0;
            if (!ok) continue;
            int row0 = bm + wm * 32 + mi * 16 + g;
            #pragma unroll
            for (int ni = 0; ni < 8; ni++) {
                int col = bn + wn * 64 + ni * 8 + t * 2;
                float* c = acc[mi][ni];
                *(float2*)(Cf + (size_t)row0 * HDIM + col)       = make_float2(c[0], c[1]);
                *(float2*)(Cf + (size_t)(row0 + 8) * HDIM + col) = make_float2(c[2], c[3]);
            }
        }
    }
    if (Opk) {
        #pragma unroll
        for (int mi = 0; mi < 2; mi++) {
            bool ok = mi ? ok1 : ok0;
            if (!ok) continue;
            int mt = mtA + mi;
            #pragma unroll
            for (int nip = 0; nip < 4; nip++) {
                float* c0 = acc[mi][nip * 2];
                float* c1 = acc[mi][nip * 2 + 1];
                uint4 h, l;
                split2(c0[0], c0[1], h.x, l.x);
                split2(c0[2], c0[3], h.y, l.y);
                split2(c1[0], c1[1], h.z, l.z);
                split2(c1[2], c1[3], h.w, l.w);
                int k16o = (bn + wn * 64 + nip * 16) >> 4;
                size_t o = ((size_t)(mt * 16 + k16o) * 2) * 32 + lane;
                Opk[o] = h;
                Opk[o + 32] = l;
            }
        }
    }
}

// ---------------- launch ----------------
extern "C" void kernel_launch(void* const* d_in, const int* in_sizes, int n_in,
                              void* d_out, int out_size)
{
    const float* x         = (const float*)d_in[0];
    const void*  edge_idx  = d_in[1];
    const float* edge_attr = (const float*)d_in[2];
    const float* We        = (const float*)d_in[3];
    const float* be        = (const float*)d_in[4];
    const float* Wm        = (const float*)d_in[5];
    const float* bmv       = (const float*)d_in[6];
    const float* pW1       = (const float*)d_in[7];
    const float* pb1       = (const float*)d_in[8];
    const float* pW2       = (const float*)d_in[9];
    const float* pb2       = (const float*)d_in[10];
    float* out             = (float*)d_out;

    float *xcur;
    uint4 *apk;
    uint2 *bpk;
    cudaGetSymbolAddress((void**)&xcur, g_xcur);
    cudaGetSymbolAddress((void**)&apk,  g_apk);
    cudaGetSymbolAddress((void**)&bpk,  g_bpk);
    uint4* apk0 = apk;
    uint4* apk1 = apk + (size_t)MT * 16 * 2 * 32;

    static int smem_set = 0;
    if (!smem_set) {
        cudaFuncSetAttribute(gemm_bf, cudaFuncAttributeMaxDynamicSharedMemorySize, GSMEM);
        smem_set = 1;
    }

    dim3 ggrid((N_NODES + 127) / 128, 2);          // 391 x 2
    const size_t BW = (size_t)8 * 32 * 2 * 2 * 32; // uint2 per weight

    detect_zero_kernel<<<(N_NODES + 255) / 256, 256>>>((const unsigned*)edge_idx);
    convert_hist_kernel<<<(N_EDGES + 255) / 256, 256>>>(edge_idx);
    scan_kernel<<<1, SCAN_T>>>();
    scatter_kernel<<<(N_EDGES + 255) / 256, 256>>>(edge_attr);
    prep_w<<<dim3(16, 32, NWEIGHTS), 32>>>(Wm, pW1, pW2);

    for (int l = 0; l < N_LAYERS; l++) {
        const float* Wel = We + (size_t)l * 3 * HDIM;
        const float* bel = be + (size_t)l * HDIM;
        const float* bml = bmv + (size_t)l * 3 * HDIM;
        const int w0 = l * 3;
        const float* xin = (l == 0) ? x : xcur;    // layer 0 reads the input directly

        edge_pack<<<MT, 512>>>(xin, Wel, bel, apk0);

        gemm_bf<<<ggrid, 256, GSMEM>>>(apk0, bpk + (w0+0)*BW, bml,          nullptr, apk1, nullptr, 1);
        gemm_bf<<<ggrid, 256, GSMEM>>>(apk1, bpk + (w0+1)*BW, bml + HDIM,   nullptr, apk0, nullptr, 1);
        gemm_bf<<<ggrid, 256, GSMEM>>>(apk0, bpk + (w0+2)*BW, bml + 2*HDIM, xcur,    apk1, xin,     2);
    }
    gemm_bf<<<ggrid, 256, GSMEM>>>(apk1, bpk + 9*BW,  pb1, nullptr, apk0, nullptr, 1);
    gemm_bf<<<ggrid, 256, GSMEM>>>(apk0, bpk + 10*BW, pb2, out,     nullptr, nullptr, 0);
}

// round 15
// speedup vs baseline: 1.3563x; 1.1128x over previous
#include <cuda_runtime.h>
#include <cuda_fp16.h>
#include <cstdint>

#define N_NODES 50000
#define N_EDGES 800000
#define HDIM    256
#define N_LAYERS 3
#define NWEIGHTS 11
#define MT 3125                 // 16-row tiles in M (50000/16 exactly)

// ---------------- scratch (no allocation allowed) ----------------
__device__ float g_xcur[N_NODES * HDIM];
__device__ uint4 g_apk[2][(size_t)MT * 16 * 2 * 32];
// packed fp16 weights (single term): [w][ch(8)][n8(32)][k2(2)][lane(32)] uint2
__device__ uint2 g_bpk[(size_t)NWEIGHTS * 8 * 32 * 2 * 32];
__device__ int   g_src [N_EDGES];
__device__ int   g_dst [N_EDGES];
__device__ float4 g_easrt[N_EDGES];      // sorted-by-dst: (a0,a1,a2, src-as-int)
__device__ int   g_cnt  [N_NODES];
__device__ int   g_start[N_NODES + 1];
__device__ int   g_fill [N_NODES];
__device__ int   g_is64;

// ---------------- helpers ----------------
__device__ __forceinline__ uint32_t smem_u32(const void* p) {
    uint32_t a;
    asm("{ .reg .u64 t; cvta.to.shared.u64 t, %1; cvt.u32.u64 %0, t; }" : "=r"(a) : "l"(p));
    return a;
}
__device__ __forceinline__ void cpa16(uint32_t dst, const void* src) {
    asm volatile("cp.async.cg.shared.global [%0], [%1], 16;" :: "r"(dst), "l"(src) : "memory");
}
// fp16 pack single
__device__ __forceinline__ uint32_t pkh(float v0, float v1) {
    __half2 hh = __floats2half2_rn(v0, v1);
    return *(uint32_t*)&hh;
}
// fp16 split: h = rn(v), l = rn(v - h)
__device__ __forceinline__ void split2h(float v0, float v1, uint32_t& h, uint32_t& l) {
    __half2 hh = __floats2half2_rn(v0, v1);
    float r0 = __low2float(hh), r1 = __high2float(hh);
    __half2 ll = __floats2half2_rn(v0 - r0, v1 - r1);
    h = *(uint32_t*)&hh;
    l = *(uint32_t*)&ll;
}
__device__ __forceinline__ void mma16(float* c, const uint4& a, uint32_t b0, uint32_t b1) {
    asm volatile("mma.sync.aligned.m16n8k16.row.col.f32.f16.f16.f32 "
                 "{%0,%1,%2,%3},{%4,%5,%6,%7},{%8,%9},{%0,%1,%2,%3};"
                 : "+f"(c[0]), "+f"(c[1]), "+f"(c[2]), "+f"(c[3])
                 : "r"(a.x), "r"(a.y), "r"(a.z), "r"(a.w), "r"(b0), "r"(b1));
}

// ---------------- index prep ----------------
__global__ void detect_zero_kernel(const unsigned* __restrict__ ei) {
    int i = blockIdx.x * blockDim.x + threadIdx.x;
    if (i < N_NODES) g_cnt[i] = 0;
    if (i == 0) {
        int all0 = 1;
        #pragma unroll 1
        for (int j = 1; j < 128; j += 2) if (ei[j] != 0u) { all0 = 0; break; }
        g_is64 = all0;
    }
}
__global__ void convert_hist_kernel(const void* __restrict__ ei) {
    int i = blockIdx.x * blockDim.x + threadIdx.x;
    if (i >= N_EDGES) return;
    int s, d;
    if (g_is64) {
        const long long* p = (const long long*)ei;
        s = (int)p[i];
        d = (int)p[N_EDGES + i];
    } else {
        const int* p = (const int*)ei;
        s = p[i];
        d = p[N_EDGES + i];
    }
    g_src[i] = s;
    g_dst[i] = d;
    atomicAdd(&g_cnt[d], 1);
}
#define SCAN_T 1024
#define SCAN_C 49
__global__ __launch_bounds__(SCAN_T) void scan_kernel() {
    __shared__ int ssum[SCAN_T];
    int tid = threadIdx.x;
    int base = tid * SCAN_C;
    int s = 0;
    #pragma unroll 1
    for (int j = 0; j < SCAN_C; j++) {
        int idx = base + j;
        if (idx < N_NODES) s += g_cnt[idx];
    }
    ssum[tid] = s;
    __syncthreads();
    #pragma unroll 1
    for (int off = 1; off < SCAN_T; off <<= 1) {
        int v = (tid >= off) ? ssum[tid - off] : 0;
        __syncthreads();
        ssum[tid] += v;
        __syncthreads();
    }
    int run = ssum[tid] - s;
    #pragma unroll 1
    for (int j = 0; j < SCAN_C; j++) {
        int idx = base + j;
        if (idx < N_NODES) {
            g_start[idx] = run;
            g_fill[idx]  = run;
            run += g_cnt[idx];
        }
    }
    if (tid == 0) g_start[N_NODES] = N_EDGES;
}
__global__ void scatter_kernel(const float* __restrict__ edge_attr) {
    int i = blockIdx.x * blockDim.x + threadIdx.x;
    if (i >= N_EDGES) return;
    int d = g_dst[i];
    int pos = atomicAdd(&g_fill[d], 1);
    float a0 = __ldg(&edge_attr[i * 3 + 0]);
    float a1 = __ldg(&edge_attr[i * 3 + 1]);
    float a2 = __ldg(&edge_attr[i * 3 + 2]);
    g_easrt[pos] = make_float4(a0, a1, a2, __int_as_float(g_src[i]));
}

// ---------------- weight packing (single fp16 term) ----------------
__global__ void prep_w(const float* __restrict__ Wm, const float* __restrict__ pW1,
                       const float* __restrict__ pW2) {
    int w = blockIdx.z, n8 = blockIdx.y, k16 = blockIdx.x;
    int lane = threadIdx.x;
    const float* src = (w < 9) ? (Wm + (size_t)w * HDIM * HDIM) : ((w == 9) ? pW1 : pW2);
    int g = lane >> 2, t = lane & 3;
    int n = n8 * 8 + g;
    int kb = k16 * 16 + t * 2;
    float v0 = src[(size_t)kb * HDIM + n],       v1 = src[(size_t)(kb + 1) * HDIM + n];
    float w0 = src[(size_t)(kb + 8) * HDIM + n], w1 = src[(size_t)(kb + 9) * HDIM + n];
    uint2 hh;
    hh.x = pkh(v0, v1);
    hh.y = pkh(w0, w1);
    int ch = k16 >> 1, k2 = k16 & 1;
    size_t o = ((((size_t)w * 8 + ch) * 32 + n8) * 2 + k2) * 32 + lane;
    g_bpk[o] = hh;
}

// ---------------- fused edge phase + fp16 split/pack (unroll-2 edge loop) ----------------
__global__ __launch_bounds__(512) void edge_pack(
    const float* __restrict__ x,
    const float* __restrict__ We, const float* __restrict__ be,
    uint4* __restrict__ dst)
{
    __shared__ float s[16][HDIM + 2];
    int wid = threadIdx.x >> 5, lane = threadIdx.x & 31;
    int node = blockIdx.x * 16 + wid;
    int h = lane * 8;

    float w0[8], w1[8], w2[8], bb[8];
    #pragma unroll
    for (int j = 0; j < 8; j++) {
        w0[j] = __ldg(We + h + j);
        w1[j] = __ldg(We + HDIM + h + j);
        w2[j] = __ldg(We + 2 * HDIM + h + j);
        bb[j] = __ldg(be + h + j);
    }

    float c[8];
    {
        const float4* xr = (const float4*)(x + (size_t)node * HDIM + h);
        float4 v0 = __ldg(xr), v1 = __ldg(xr + 1);
        c[0] = v0.x; c[1] = v0.y; c[2] = v0.z; c[3] = v0.w;
        c[4] = v1.x; c[5] = v1.y; c[6] = v1.z; c[7] = v1.w;
    }
    int s0 = g_start[node], s1 = g_start[node + 1];
    #pragma unroll 2
    for (int j = s0; j < s1; j++) {
        float4 ea = __ldg(&g_easrt[j]);
        int src = __float_as_int(ea.w);
        const float4* xs = (const float4*)(x + (size_t)src * HDIM + h);
        float4 v0 = __ldg(xs), v1 = __ldg(xs + 1);
        float xv[8] = {v0.x, v0.y, v0.z, v0.w, v1.x, v1.y, v1.z, v1.w};
        #pragma unroll
        for (int k = 0; k < 8; k++) {
            float e = fmaf(ea.x, w0[k], fmaf(ea.y, w1[k], fmaf(ea.z, w2[k], bb[k])));
            c[k] += fmaxf(xv[k] + e, 0.f);
        }
    }
    #pragma unroll
    for (int j = 0; j < 8; j++) s[wid][h + j] = c[j];
    __syncthreads();

    // repack: warp wid handles k16 group wid
    int g = lane >> 2, t = lane & 3;
    const float* r0 = &s[g][wid * 16 + t * 2];
    const float* r1 = &s[g + 8][wid * 16 + t * 2];
    float2 v00 = make_float2(r0[0], r0[1]), v01 = make_float2(r0[8], r0[9]);
    float2 v10 = make_float2(r1[0], r1[1]), v11 = make_float2(r1[8], r1[9]);
    uint4 hh, ll;
    split2h(v00.x, v00.y, hh.x, ll.x);
    split2h(v10.x, v10.y, hh.y, ll.y);
    split2h(v01.x, v01.y, hh.z, ll.z);
    split2h(v11.x, v11.y, hh.w, ll.w);
    size_t o = ((size_t)(blockIdx.x * 16 + wid) * 2) * 32 + lane;
    dst[o] = hh;
    dst[o + 32] = ll;
}

// ---------------- fp16-split mma GEMM: A 2-term, B 1-term; 4-stage ring ----------------
#define GSMEM (4 * 8192)   // 4 x 8KB B staging = 32KB dynamic

__global__ __launch_bounds__(256, 2) void gemm_bf(
    const uint4* __restrict__ Apk, const uint2* __restrict__ Bpk,
    const float* __restrict__ bias, float* __restrict__ Cf, uint4* __restrict__ Opk,
    const float* __restrict__ res, int mode)
{
    extern __shared__ uint2 sbd[];
    const uint32_t sbase = smem_u32(sbd);
    const int tid  = threadIdx.x;
    const int lane = tid & 31;
    const int warp = tid >> 5;
    const int g = lane >> 2, t = lane & 3;
    const int wm = warp & 3;
    const int wn = warp >> 2;
    const int bm = blockIdx.x * 128;
    const int bn = blockIdx.y * 128;
    const int bn8 = bn >> 3;

    float acc[2][8][4];
    #pragma unroll
    for (int i = 0; i < 2; i++)
        #pragma unroll
        for (int j = 0; j < 8; j++)
            #pragma unroll
            for (int q = 0; q < 4; q++) acc[i][j][q] = 0.f;

    const int mtA = (bm >> 4) + wm * 2;
    const bool ok0 = (mtA + 0) < MT;
    const bool ok1 = (mtA + 1) < MT;

    auto issue = [&](int ch, int buf) {
        const uint4* src = (const uint4*)(Bpk + ((size_t)ch * 32 + bn8) * 64);
        uint32_t dst = sbase + buf * 8192 + tid * 16;
        #pragma unroll
        for (int i = 0; i < 2; i++) cpa16(dst + i * 4096, src + tid + i * 256);
        asm volatile("cp.async.commit_group;" ::: "memory");
    };
    auto ldA = [&](int k16, uint4 fr[2][2]) {
        #pragma unroll
        for (int mi = 0; mi < 2; mi++) {
            bool ok = mi ? ok1 : ok0;
            size_t o = ((size_t)((mtA + mi) * 16 + k16) * 2) * 32 + lane;
            if (ok) {
                fr[mi][0] = __ldg(Apk + o);
                fr[mi][1] = __ldg(Apk + o + 32);
            } else {
                fr[mi][0] = make_uint4(0, 0, 0, 0);
                fr[mi][1] = make_uint4(0, 0, 0, 0);
            }
        }
    };

    issue(0, 0);
    issue(1, 1);
    issue(2, 2);

    uint4 af[2][2], an[2][2];
    ldA(0, af);

    #pragma unroll 1
    for (int ch = 0; ch < 8; ch++) {
        const int buf = ch & 3;
        if (ch >= 6) {
            if (ch == 6) asm volatile("cp.async.wait_group 1;" ::: "memory");
            else         asm volatile("cp.async.wait_group 0;" ::: "memory");
        } else {
            asm volatile("cp.async.wait_group 2;" ::: "memory");
        }
        __syncthreads();
        if (ch + 3 < 8) issue(ch + 3, (ch + 3) & 3);

        #pragma unroll
        for (int k2 = 0; k2 < 2; k2++) {
            const int k16 = ch * 2 + k2;
            if (k16 < 15) ldA(k16 + 1, an);
            const uint2* bs = sbd + buf * 1024;
            uint2 bh[8];
            #pragma unroll
            for (int ni = 0; ni < 8; ni++)
                bh[ni] = bs[(wn * 8 + ni) * 64 + k2 * 32 + lane];
            #pragma unroll
            for (int mi = 0; mi < 2; mi++)
                #pragma unroll
                for (int ni = 0; ni < 8; ni++) {
                    mma16(acc[mi][ni], af[mi][0], bh[ni].x, bh[ni].y);
                    mma16(acc[mi][ni], af[mi][1], bh[ni].x, bh[ni].y);
                }
            if (k16 < 15) {
                #pragma unroll
                for (int mi = 0; mi < 2; mi++) {
                    af[mi][0] = an[mi][0];
                    af[mi][1] = an[mi][1];
                }
            }
        }
    }

    #pragma unroll
    for (int ni = 0; ni < 8; ni++) {
        int col = bn + wn * 64 + ni * 8 + t * 2;
        float2 bb = *(const float2*)(bias + col);
        #pragma unroll
        for (int mi = 0; mi < 2; mi++) {
            float* c = acc[mi][ni];
            c[0] += bb.x; c[1] += bb.y; c[2] += bb.x; c[3] += bb.y;
            if (mode >= 1) {
                c[0] = fmaxf(c[0], 0.f); c[1] = fmaxf(c[1], 0.f);
                c[2] = fmaxf(c[2], 0.f); c[3] = fmaxf(c[3], 0.f);
            }
            if (mode == 2) {
                bool ok = mi ? ok1 : ok0;
                if (ok) {
                    int row0 = bm + wm * 32 + mi * 16 + g;
                    float2 r0 = *(const float2*)(res + (size_t)row0 * HDIM + col);
                    float2 r1 = *(const float2*)(res + (size_t)(row0 + 8) * HDIM + col);
                    c[0] += r0.x; c[1] += r0.y; c[2] += r1.x; c[3] += r1.y;
                }
            }
        }
    }
    if (Cf) {
        #pragma unroll
        for (int mi = 0; mi < 2; mi++) {
            bool ok = mi ? ok1 : ok0;
            if (!ok) continue;
            int row0 = bm + wm * 32 + mi * 16 + g;
            #pragma unroll
            for (int ni = 0; ni < 8; ni++) {
                int col = bn + wn * 64 + ni * 8 + t * 2;
                float* c = acc[mi][ni];
                *(float2*)(Cf + (size_t)row0 * HDIM + col)       = make_float2(c[0], c[1]);
                *(float2*)(Cf + (size_t)(row0 + 8) * HDIM + col) = make_float2(c[2], c[3]);
            }
        }
    }
    if (Opk) {
        #pragma unroll
        for (int mi = 0; mi < 2; mi++) {
            bool ok = mi ? ok1 : ok0;
            if (!ok) continue;
            int mt = mtA + mi;
            #pragma unroll
            for (int nip = 0; nip < 4; nip++) {
                float* c0 = acc[mi][nip * 2];
                float* c1 = acc[mi][nip * 2 + 1];
                uint4 h, l;
                split2h(c0[0], c0[1], h.x, l.x);
                split2h(c0[2], c0[3], h.y, l.y);
                split2h(c1[0], c1[1], h.z, l.z);
                split2h(c1[2], c1[3], h.w, l.w);
                int k16o = (bn + wn * 64 + nip * 16) >> 4;
                size_t o = ((size_t)(mt * 16 + k16o) * 2) * 32 + lane;
                Opk[o] = h;
                Opk[o + 32] = l;
            }
        }
    }
}

// ---------------- launch ----------------
extern "C" void kernel_launch(void* const* d_in, const int* in_sizes, int n_in,
                              void* d_out, int out_size)
{
    const float* x         = (const float*)d_in[0];
    const void*  edge_idx  = d_in[1];
    const float* edge_attr = (const float*)d_in[2];
    const float* We        = (const float*)d_in[3];
    const float* be        = (const float*)d_in[4];
    const float* Wm        = (const float*)d_in[5];
    const float* bmv       = (const float*)d_in[6];
    const float* pW1       = (const float*)d_in[7];
    const float* pb1       = (const float*)d_in[8];
    const float* pW2       = (const float*)d_in[9];
    const float* pb2       = (const float*)d_in[10];
    float* out             = (float*)d_out;

    float *xcur;
    uint4 *apk;
    uint2 *bpk;
    cudaGetSymbolAddress((void**)&xcur, g_xcur);
    cudaGetSymbolAddress((void**)&apk,  g_apk);
    cudaGetSymbolAddress((void**)&bpk,  g_bpk);
    uint4* apk0 = apk;
    uint4* apk1 = apk + (size_t)MT * 16 * 2 * 32;

    static int smem_set = 0;
    if (!smem_set) {
        cudaFuncSetAttribute(gemm_bf, cudaFuncAttributeMaxDynamicSharedMemorySize, GSMEM);
        smem_set = 1;
    }

    dim3 ggrid((N_NODES + 127) / 128, 2);          // 391 x 2
    const size_t BW = (size_t)8 * 32 * 2 * 32;     // uint2 per weight

    detect_zero_kernel<<<(N_NODES + 255) / 256, 256>>>((const unsigned*)edge_idx);
    convert_hist_kernel<<<(N_EDGES + 255) / 256, 256>>>(edge_idx);
    scan_kernel<<<1, SCAN_T>>>();
    scatter_kernel<<<(N_EDGES + 255) / 256, 256>>>(edge_attr);
    prep_w<<<dim3(16, 32, NWEIGHTS), 32>>>(Wm, pW1, pW2);

    for (int l = 0; l < N_LAYERS; l++) {
        const float* Wel = We + (size_t)l * 3 * HDIM;
        const float* bel = be + (size_t)l * HDIM;
        const float* bml = bmv + (size_t)l * 3 * HDIM;
        const int w0 = l * 3;
        const float* xin = (l == 0) ? x : xcur;    // layer 0 reads the input directly

        edge_pack<<<MT, 512>>>(xin, Wel, bel, apk0);

        gemm_bf<<<ggrid, 256, GSMEM>>>(apk0, bpk + (w0+0)*BW, bml,          nullptr, apk1, nullptr, 1);
        gemm_bf<<<ggrid, 256, GSMEM>>>(apk1, bpk + (w0+1)*BW, bml + HDIM,   nullptr, apk0, nullptr, 1);
        gemm_bf<<<ggrid, 256, GSMEM>>>(apk0, bpk + (w0+2)*BW, bml + 2*HDIM, xcur,    apk1, xin,     2);
    }
    gemm_bf<<<ggrid, 256, GSMEM>>>(apk1, bpk + 9*BW,  pb1, nullptr, apk0, nullptr, 1);
    gemm_bf<<<ggrid, 256, GSMEM>>>(apk0, bpk + 10*BW, pb2, out,     nullptr, nullptr, 0);
}